// round 2
// baseline (speedup 1.0000x reference)
#include <cuda_runtime.h>

// LayerNorm backward fused: golden_x [B,S,H], golden_gamma [H], golden_beta [H]
// B=4, S=4096, H=2048, fp32. Output layout: [x | gamma | beta] concatenated.

#define HF 2048
#define ROWS 16384          // B*S
#define THREADS 256
#define GRID 592            // 148 SMs * 4

__global__ void zero_param_grads(float* __restrict__ out) {
    int i = blockIdx.x * blockDim.x + threadIdx.x;
    if (i < 2 * HF) out[(size_t)ROWS * HF + i] = 0.0f;
}

__global__ __launch_bounds__(THREADS) void ln_bwd_kernel(
    const float* __restrict__ dy,
    const float* __restrict__ x1,
    const float* __restrict__ x2,
    const float* __restrict__ rstd,
    const float* __restrict__ mean,
    const float* __restrict__ gamma,
    const float* __restrict__ dsum,
    float* __restrict__ out)
{
    __shared__ float sm[3][8];

    const int tid  = threadIdx.x;
    const int lane = tid & 31;
    const int wid  = tid >> 5;

    // Each thread owns 8 fixed columns: [c0..c0+3] and [c1..c1+3]
    const int c0 = 4 * tid;          // 0..1020
    const int c1 = c0 + HF / 2;      // 1024..2044

    // gamma: loaded once, reused across all rows (register-resident)
    const float4 g0 = *(const float4*)(gamma + c0);
    const float4 g1 = *(const float4*)(gamma + c1);
    float gv[8] = {g0.x, g0.y, g0.z, g0.w, g1.x, g1.y, g1.z, g1.w};

    // per-thread partial dgamma / dbeta accumulators (fixed column mapping)
    float ag[8] = {0.f, 0.f, 0.f, 0.f, 0.f, 0.f, 0.f, 0.f};
    float ab[8] = {0.f, 0.f, 0.f, 0.f, 0.f, 0.f, 0.f, 0.f};

    const float inv_d = 1.0f / (float)HF;

    for (int row = blockIdx.x; row < ROWS; row += GRID) {
        const size_t base = (size_t)row * HF;

        const float4 dy0 = *(const float4*)(dy + base + c0);
        const float4 dy1 = *(const float4*)(dy + base + c1);
        const float4 a0  = *(const float4*)(x1 + base + c0);
        const float4 a1  = *(const float4*)(x1 + base + c1);
        const float4 b0  = *(const float4*)(x2 + base + c0);
        const float4 b1  = *(const float4*)(x2 + base + c1);
        const float4 d0  = *(const float4*)(dsum + base + c0);
        const float4 d1  = *(const float4*)(dsum + base + c1);
        const float mu = mean[row];
        const float rs = rstd[row];

        float dyv[8] = {dy0.x, dy0.y, dy0.z, dy0.w, dy1.x, dy1.y, dy1.z, dy1.w};
        float xh[8]  = {a0.x + b0.x - mu, a0.y + b0.y - mu,
                        a0.z + b0.z - mu, a0.w + b0.w - mu,
                        a1.x + b1.x - mu, a1.y + b1.y - mu,
                        a1.z + b1.z - mu, a1.w + b1.w - mu};
        float dsv[8] = {d0.x, d0.y, d0.z, d0.w, d1.x, d1.y, d1.z, d1.w};

        // local partial sums
        float s1 = 0.f, s2 = 0.f, s3 = 0.f;
        #pragma unroll
        for (int i = 0; i < 8; i++) {
            const float pdxl = dyv[i] * gv[i];
            s1 = fmaf(pdxl, xh[i], s1);
            s2 += pdxl;
            s3 += xh[i];
        }

        // warp reduce
        #pragma unroll
        for (int off = 16; off > 0; off >>= 1) {
            s1 += __shfl_xor_sync(0xFFFFFFFFu, s1, off);
            s2 += __shfl_xor_sync(0xFFFFFFFFu, s2, off);
            s3 += __shfl_xor_sync(0xFFFFFFFFu, s3, off);
        }

        // cross-warp reduce via smem (broadcast reads to avoid a 3rd barrier)
        __syncthreads();   // protect smem from previous iteration's readers
        if (lane == 0) { sm[0][wid] = s1; sm[1][wid] = s2; sm[2][wid] = s3; }
        __syncthreads();
        float t1 = 0.f, t2 = 0.f, t3 = 0.f;
        #pragma unroll
        for (int w = 0; w < 8; w++) { t1 += sm[0][w]; t2 += sm[1][w]; t3 += sm[2][w]; }

        const float rs3     = rs * rs * rs;
        const float pd_var  = -0.5f * t1 * rs3;
        const float pd_mean = -t2 * rs + pd_var * (-2.0f * inv_d) * t3;
        const float coef    = pd_var * (2.0f * inv_d);
        const float cmean   = pd_mean * inv_d;

        float ov[8];
        #pragma unroll
        for (int i = 0; i < 8; i++) {
            const float pdxl = dyv[i] * gv[i];
            ov[i] = fmaf(pdxl, rs, fmaf(coef, xh[i], cmean)) + dsv[i];
            // param-grad accumulators
            ag[i] = fmaf(dyv[i] * xh[i], rs, ag[i]);
            ab[i] += dyv[i];
        }

        *(float4*)(out + base + c0) = make_float4(ov[0], ov[1], ov[2], ov[3]);
        *(float4*)(out + base + c1) = make_float4(ov[4], ov[5], ov[6], ov[7]);
    }

    // flush dgamma/dbeta partials: 592 CTAs * 4096 atomics -> negligible
    float* gout = out + (size_t)ROWS * HF;
    float* bout = gout + HF;
    #pragma unroll
    for (int i = 0; i < 4; i++) {
        atomicAdd(gout + c0 + i, ag[i]);
        atomicAdd(gout + c1 + i, ag[4 + i]);
        atomicAdd(bout + c0 + i, ab[i]);
        atomicAdd(bout + c1 + i, ab[4 + i]);
    }
}

extern "C" void kernel_launch(void* const* d_in, const int* in_sizes, int n_in,
                              void* d_out, int out_size) {
    const float* dy    = (const float*)d_in[0];
    const float* x1    = (const float*)d_in[1];
    const float* x2    = (const float*)d_in[2];
    const float* rstd  = (const float*)d_in[3];
    const float* mean  = (const float*)d_in[4];
    const float* gamma = (const float*)d_in[5];
    const float* dsum  = (const float*)d_in[6];
    float* out = (float*)d_out;

    zero_param_grads<<<(2 * HF + 255) / 256, 256>>>(out);
    ln_bwd_kernel<<<GRID, THREADS>>>(dy, x1, x2, rstd, mean, gamma, dsum, out);
}

// round 3
// speedup vs baseline: 1.2140x; 1.2140x over previous
#include <cuda_runtime.h>

// LayerNorm backward fused: golden_x [B,S,H], golden_gamma [H], golden_beta [H]
// B=4, S=4096, H=2048, fp32. Output layout: [x | gamma | beta] concatenated.
// R2: software-pipelined row loop (prefetch next row during reduction),
//     single-barrier double-buffered smem reduction, streaming ld/st hints.

#define HF 2048
#define ROWS 16384          // B*S
#define THREADS 256
#define GRID 296            // 148 SMs * 2 CTAs/SM -> single persistent wave

__global__ void zero_param_grads(float* __restrict__ out) {
    int i = blockIdx.x * blockDim.x + threadIdx.x;
    if (i < 2 * HF) out[(size_t)ROWS * HF + i] = 0.0f;
}

__global__ __launch_bounds__(THREADS, 2) void ln_bwd_kernel(
    const float* __restrict__ dy,
    const float* __restrict__ x1,
    const float* __restrict__ x2,
    const float* __restrict__ rstd,
    const float* __restrict__ mean,
    const float* __restrict__ gamma,
    const float* __restrict__ dsum,
    float* __restrict__ out)
{
    __shared__ float sm[2][3][8];

    const int tid  = threadIdx.x;
    const int lane = tid & 31;
    const int wid  = tid >> 5;

    // Each thread owns 8 fixed columns: [c0..c0+3] and [c1..c1+3]
    const int c0 = 4 * tid;          // 0..1020
    const int c1 = c0 + HF / 2;      // 1024..2044

    // gamma: loaded once, reused across all rows (register-resident)
    const float4 g0 = *(const float4*)(gamma + c0);
    const float4 g1 = *(const float4*)(gamma + c1);
    float gv[8] = {g0.x, g0.y, g0.z, g0.w, g1.x, g1.y, g1.z, g1.w};

    // per-thread partial dgamma / dbeta accumulators (fixed column mapping)
    float ag[8] = {0.f, 0.f, 0.f, 0.f, 0.f, 0.f, 0.f, 0.f};
    float ab[8] = {0.f, 0.f, 0.f, 0.f, 0.f, 0.f, 0.f, 0.f};

    const float inv_d = 1.0f / (float)HF;

    // ---- pipeline prologue: load first row ----
    float4 Pdy0, Pdy1, Pa0, Pa1, Pb0, Pb1, Pd0, Pd1;
    float  Pmu = 0.f, Prs = 0.f;
    {
        const size_t base = (size_t)blockIdx.x * HF;
        Pdy0 = __ldcs((const float4*)(dy + base + c0));
        Pdy1 = __ldcs((const float4*)(dy + base + c1));
        Pa0  = __ldcs((const float4*)(x1 + base + c0));
        Pa1  = __ldcs((const float4*)(x1 + base + c1));
        Pb0  = __ldcs((const float4*)(x2 + base + c0));
        Pb1  = __ldcs((const float4*)(x2 + base + c1));
        Pd0  = __ldcs((const float4*)(dsum + base + c0));
        Pd1  = __ldcs((const float4*)(dsum + base + c1));
        Pmu  = mean[blockIdx.x];
        Prs  = rstd[blockIdx.x];
    }

    int parity = 0;
    for (int row = blockIdx.x; row < ROWS; row += GRID) {
        const size_t base = (size_t)row * HF;

        // consume the prefetched row into working values
        float dyv[8] = {Pdy0.x, Pdy0.y, Pdy0.z, Pdy0.w,
                        Pdy1.x, Pdy1.y, Pdy1.z, Pdy1.w};
        const float mu = Pmu;
        const float rs = Prs;
        float xh[8]  = {Pa0.x + Pb0.x - mu, Pa0.y + Pb0.y - mu,
                        Pa0.z + Pb0.z - mu, Pa0.w + Pb0.w - mu,
                        Pa1.x + Pb1.x - mu, Pa1.y + Pb1.y - mu,
                        Pa1.z + Pb1.z - mu, Pa1.w + Pb1.w - mu};
        float dsv[8] = {Pd0.x, Pd0.y, Pd0.z, Pd0.w,
                        Pd1.x, Pd1.y, Pd1.z, Pd1.w};

        // ---- prefetch next row NOW: these LDGs stay in flight through the
        //      reduction barrier + epilogue + store below ----
        const int nrow = row + GRID;
        if (nrow < ROWS) {
            const size_t nb = (size_t)nrow * HF;
            Pdy0 = __ldcs((const float4*)(dy + nb + c0));
            Pdy1 = __ldcs((const float4*)(dy + nb + c1));
            Pa0  = __ldcs((const float4*)(x1 + nb + c0));
            Pa1  = __ldcs((const float4*)(x1 + nb + c1));
            Pb0  = __ldcs((const float4*)(x2 + nb + c0));
            Pb1  = __ldcs((const float4*)(x2 + nb + c1));
            Pd0  = __ldcs((const float4*)(dsum + nb + c0));
            Pd1  = __ldcs((const float4*)(dsum + nb + c1));
            Pmu  = mean[nrow];
            Prs  = rstd[nrow];
        }

        // local partial sums
        float s1 = 0.f, s2 = 0.f, s3 = 0.f;
        #pragma unroll
        for (int i = 0; i < 8; i++) {
            const float pdxl = dyv[i] * gv[i];
            s1 = fmaf(pdxl, xh[i], s1);
            s2 += pdxl;
            s3 += xh[i];
        }

        // warp reduce (3 independent chains, shfls overlap)
        #pragma unroll
        for (int off = 16; off > 0; off >>= 1) {
            s1 += __shfl_xor_sync(0xFFFFFFFFu, s1, off);
            s2 += __shfl_xor_sync(0xFFFFFFFFu, s2, off);
            s3 += __shfl_xor_sync(0xFFFFFFFFu, s3, off);
        }

        // cross-warp reduce: double-buffered smem -> single barrier per row
        if (lane == 0) {
            sm[parity][0][wid] = s1;
            sm[parity][1][wid] = s2;
            sm[parity][2][wid] = s3;
        }
        __syncthreads();
        float t1 = 0.f, t2 = 0.f, t3 = 0.f;
        #pragma unroll
        for (int w = 0; w < 8; w++) {
            t1 += sm[parity][0][w];
            t2 += sm[parity][1][w];
            t3 += sm[parity][2][w];
        }
        parity ^= 1;

        const float rs3     = rs * rs * rs;
        const float pd_var  = -0.5f * t1 * rs3;
        const float pd_mean = -t2 * rs + pd_var * (-2.0f * inv_d) * t3;
        const float coef    = pd_var * (2.0f * inv_d);
        const float cmean   = pd_mean * inv_d;

        float ov[8];
        #pragma unroll
        for (int i = 0; i < 8; i++) {
            const float pdxl = dyv[i] * gv[i];
            ov[i] = fmaf(pdxl, rs, fmaf(coef, xh[i], cmean)) + dsv[i];
            // param-grad accumulators
            ag[i] = fmaf(dyv[i] * xh[i], rs, ag[i]);
            ab[i] += dyv[i];
        }

        __stcs((float4*)(out + base + c0), make_float4(ov[0], ov[1], ov[2], ov[3]));
        __stcs((float4*)(out + base + c1), make_float4(ov[4], ov[5], ov[6], ov[7]));
    }

    // flush dgamma/dbeta partials: 296 CTAs * 4096 atomics -> negligible
    float* gout = out + (size_t)ROWS * HF;
    float* bout = gout + HF;
    #pragma unroll
    for (int i = 0; i < 4; i++) {
        atomicAdd(gout + c0 + i, ag[i]);
        atomicAdd(gout + c1 + i, ag[4 + i]);
        atomicAdd(bout + c0 + i, ab[i]);
        atomicAdd(bout + c1 + i, ab[4 + i]);
    }
}

extern "C" void kernel_launch(void* const* d_in, const int* in_sizes, int n_in,
                              void* d_out, int out_size) {
    const float* dy    = (const float*)d_in[0];
    const float* x1    = (const float*)d_in[1];
    const float* x2    = (const float*)d_in[2];
    const float* rstd  = (const float*)d_in[3];
    const float* mean  = (const float*)d_in[4];
    const float* gamma = (const float*)d_in[5];
    const float* dsum  = (const float*)d_in[6];
    float* out = (float*)d_out;

    zero_param_grads<<<(2 * HF + 255) / 256, 256>>>(out);
    ln_bwd_kernel<<<GRID, THREADS>>>(dy, x1, x2, rstd, mean, gamma, dsum, out);
}